// round 9
// baseline (speedup 1.0000x reference)
#include <cuda_runtime.h>

// Problem constants
#define D_TOT   1296
#define K_PTS   64
#define R_RANK  16
#define F_SUB   408
#define DT      (200.0f / 64.0f)
#define D_PER_BLOCK 2
#define GRID_A  (D_TOT / D_PER_BLOCK)      // 648
#define OUT_SCALE (DT / (float)D_TOT)

#define OUT_INTERLEAVED 0
#define OUT_REAL_ONLY   1

// Per-block partials, fully overwritten every replay (no zeroing, no atomics).
// Layout per block: [tid*32 + 0..15] = T_re, [tid*32 + 16..31] = T_im,
//                   [8192 + tid] = M1_re, [8448 + tid] = M1_im.
#define PART_LEN 8704
#define RED_CHUNKS 12
#define RED_BPC (GRID_A / RED_CHUNKS)      // 54
__device__ float g_part[GRID_A][PART_LEN];   // 22.6 MB
__device__ float g_part2[RED_CHUNKS][PART_LEN];
__device__ float g_acc[PART_LEN];

// ---- kernel A (FIRST launch -> ncu profiles this one) ----
// Thread owns (i = tid>>4, j = tid&15); 16 complex T accumulators.
__global__ __launch_bounds__(256) void accum_kernel(
    const float* __restrict__ att_re, const float* __restrict__ att_im,
    const float* __restrict__ rad_re, const float* __restrict__ rad_im)
{
    __shared__ __align__(16) float2 s_a[K_PTS * R_RANK];   // att interleaved
    __shared__ __align__(16) float2 s_b[K_PTS * R_RANK];   // rad interleaved
    __shared__ __align__(16) float  s_cre[K_PTS * R_RANK];
    __shared__ __align__(16) float  s_cim[K_PTS * R_RANK];
    __shared__ float s_chunk[2][4][16];                    // scan partials

    const int tid = threadIdx.x;
    const int i = tid >> 4;
    const int j = tid & 15;

    float tre[16], tim[16];
#pragma unroll
    for (int l = 0; l < 16; ++l) { tre[l] = 0.0f; tim[l] = 0.0f; }
    float m1r = 0.0f, m1i = 0.0f;

    for (int dd = 0; dd < D_PER_BLOCK; ++dd) {
        const int d = blockIdx.x * D_PER_BLOCK + dd;
        const long base4 = (long)d * (K_PTS * R_RANK / 4);
        {
            float4 ar4 = reinterpret_cast<const float4*>(att_re)[base4 + tid];
            float4 ai4 = reinterpret_cast<const float4*>(att_im)[base4 + tid];
            float4 br4 = reinterpret_cast<const float4*>(rad_re)[base4 + tid];
            float4 bi4 = reinterpret_cast<const float4*>(rad_im)[base4 + tid];
            const int o = tid * 4;
            s_a[o + 0] = make_float2(ar4.x, ai4.x);
            s_a[o + 1] = make_float2(ar4.y, ai4.y);
            s_a[o + 2] = make_float2(ar4.z, ai4.z);
            s_a[o + 3] = make_float2(ar4.w, ai4.w);
            s_b[o + 0] = make_float2(br4.x, bi4.x);
            s_b[o + 1] = make_float2(br4.y, bi4.y);
            s_b[o + 2] = make_float2(br4.z, bi4.z);
            s_b[o + 3] = make_float2(br4.w, bi4.w);
        }
        __syncthreads();

        // Two-phase parallel cumsum: c[k][l] = DT * cumsum_k(att[k][l]).
        const int l_s = tid & 15;
        const int plane = (tid >> 4) & 1;
        const int q = tid >> 5;
        if (tid < 128) {
            float sum = 0.0f;
#pragma unroll
            for (int kk = 0; kk < 16; ++kk) {
                float2 v = s_a[(q * 16 + kk) * 16 + l_s];
                sum += plane ? v.y : v.x;
            }
            s_chunk[plane][q][l_s] = sum;
        }
        __syncthreads();
        if (tid < 128) {
            float run = 0.0f;
#pragma unroll
            for (int qq = 0; qq < 3; ++qq)
                if (qq < q) run += s_chunk[plane][qq][l_s];
            float* dst = plane ? s_cim : s_cre;
#pragma unroll
            for (int kk = 0; kk < 16; ++kk) {
                float2 v = s_a[(q * 16 + kk) * 16 + l_s];
                run += plane ? v.y : v.x;
                dst[(q * 16 + kk) * 16 + l_s] = DT * run;
            }
        }
        __syncthreads();

        // k = 0 peel: first order (M1) only
        {
            float2 a = s_a[j];
            float2 b = s_b[i];
            m1r += b.x * a.x - b.y * a.y;
            m1i -= b.x * a.y + b.y * a.x;
        }

#pragma unroll 1
        for (int k = 1; k < K_PTS; ++k) {
            float2 a = s_a[k * 16 + j];
            float2 b = s_b[k * 16 + i];
            // w = conj(rad_i) * conj(att_j)
            float wr = fmaf(b.x, a.x, -b.y * a.y);
            float wi = -fmaf(b.x, a.y, b.y * a.x);
            m1r += wr;
            m1i += wi;

            const float4* cr4 = reinterpret_cast<const float4*>(s_cre + k * 16);
            const float4* ci4 = reinterpret_cast<const float4*>(s_cim + k * 16);
#pragma unroll
            for (int p = 0; p < 4; ++p) {
                float4 cr = cr4[p];
                float4 ci = ci4[p];
                tre[4*p+0] = fmaf(wr, cr.x, fmaf(-wi, ci.x, tre[4*p+0]));
                tim[4*p+0] = fmaf(wr, ci.x, fmaf( wi, cr.x, tim[4*p+0]));
                tre[4*p+1] = fmaf(wr, cr.y, fmaf(-wi, ci.y, tre[4*p+1]));
                tim[4*p+1] = fmaf(wr, ci.y, fmaf( wi, cr.y, tim[4*p+1]));
                tre[4*p+2] = fmaf(wr, cr.z, fmaf(-wi, ci.z, tre[4*p+2]));
                tim[4*p+2] = fmaf(wr, ci.z, fmaf( wi, cr.z, tim[4*p+2]));
                tre[4*p+3] = fmaf(wr, cr.w, fmaf(-wi, ci.w, tre[4*p+3]));
                tim[4*p+3] = fmaf(wr, ci.w, fmaf( wi, cr.w, tim[4*p+3]));
            }
        }
        __syncthreads();   // before next dd overwrites shared
    }

    // Write per-block partials (coalesced float4 stores)
    float* pT = g_part[blockIdx.x] + tid * 32;
#pragma unroll
    for (int p = 0; p < 4; ++p)
        reinterpret_cast<float4*>(pT)[p] =
            make_float4(tre[4*p], tre[4*p+1], tre[4*p+2], tre[4*p+3]);
#pragma unroll
    for (int p = 0; p < 4; ++p)
        reinterpret_cast<float4*>(pT + 16)[p] =
            make_float4(tim[4*p], tim[4*p+1], tim[4*p+2], tim[4*p+3]);
    g_part[blockIdx.x][8192 + tid] = m1r;
    g_part[blockIdx.x][8448 + tid] = m1i;
}

// ---- reduce stage 1: fold 54 partials per chunk (grid 34 x 12) ----
__global__ __launch_bounds__(256) void reduce1_kernel() {
    const int v = blockIdx.x * 256 + threadIdx.x;   // 34*256 = 8704
    const int c = blockIdx.y;
    const int b0 = c * RED_BPC;
    float s0 = 0.f, s1 = 0.f, s2 = 0.f, s3 = 0.f, s4 = 0.f, s5 = 0.f;
#pragma unroll 1
    for (int n = 0; n < RED_BPC; n += 6) {          // 54 = 9*6
        s0 += g_part[b0 + n + 0][v];
        s1 += g_part[b0 + n + 1][v];
        s2 += g_part[b0 + n + 2][v];
        s3 += g_part[b0 + n + 3][v];
        s4 += g_part[b0 + n + 4][v];
        s5 += g_part[b0 + n + 5][v];
    }
    g_part2[c][v] = ((s0 + s1) + (s2 + s3)) + (s4 + s5);
}

// ---- reduce stage 2: fold 12 chunk sums (grid 34) ----
__global__ __launch_bounds__(256) void reduce2_kernel() {
    const int v = blockIdx.x * 256 + threadIdx.x;
    float s = 0.0f;
#pragma unroll
    for (int c = 0; c < RED_CHUNKS; ++c) s += g_part2[c][v];
    g_acc[v] = s;
}

// ---- kernel B: contract with f_i f_j f_l and reduce to csi[f] ----
__global__ __launch_bounds__(256) void csi_kernel(
    const float* __restrict__ f_re, const float* __restrict__ f_im,
    float* __restrict__ out, int mode)
{
    const int f   = blockIdx.x;
    const int tid = threadIdx.x;
    const int i = tid >> 4;
    const int j = tid & 15;

    __shared__ float sfr[16], sfi[16];
    if (tid < 16) { sfr[tid] = f_re[f * R_RANK + tid]; sfi[tid] = f_im[f * R_RANK + tid]; }
    __syncthreads();

    // inner = M1[ij] + sum_l f_l * T[ij][l]
    float sr = g_acc[8192 + tid], si = g_acc[8448 + tid];
    const float* tr_p = g_acc + tid * 32;
    const float* ti_p = tr_p + 16;
#pragma unroll
    for (int l = 0; l < 16; ++l) {
        float tr = tr_p[l];
        float ti = ti_p[l];
        float fr = sfr[l], fi = sfi[l];
        sr = fmaf(tr, fr, fmaf(-ti, fi, sr));
        si = fmaf(tr, fi, fmaf( ti, fr, si));
    }
    // val = (f_i * f_j) * inner
    float fir = sfr[i], fii = sfi[i];
    float fjr = sfr[j], fji = sfi[j];
    float pr = fir * fjr - fii * fji;
    float pi = fir * fji + fii * fjr;
    float vr = pr * sr - pi * si;
    float vi = pr * si + pi * sr;

    __shared__ float red_r[256], red_i[256];
    red_r[tid] = vr; red_i[tid] = vi;
    __syncthreads();
#pragma unroll
    for (int s = 128; s > 0; s >>= 1) {
        if (tid < s) {
            red_r[tid] += red_r[tid + s];
            red_i[tid] += red_i[tid + s];
        }
        __syncthreads();
    }
    if (tid == 0) {
        float re = red_r[0] * OUT_SCALE;
        float im = red_i[0] * OUT_SCALE;
        if (mode == OUT_REAL_ONLY) {
            out[f] = re;                       // float32(csi) == Re(csi)
        } else {
            out[2 * f]     = re;
            out[2 * f + 1] = im;
        }
    }
}

extern "C" void kernel_launch(void* const* d_in, const int* in_sizes, int n_in,
                              void* d_out, int out_size)
{
    // Established (round 6 PASS): out_size == 408 -> real-part-only output,
    // inputs in dict/signature order.
    const float *att_re, *att_im, *rad_re, *rad_im, *f_re, *f_im;
    int mode;

    if (out_size == F_SUB) {
        att_re = (const float*)d_in[0];
        att_im = (const float*)d_in[1];
        rad_re = (const float*)d_in[2];
        rad_im = (const float*)d_in[3];
        mode = OUT_REAL_ONLY;
    } else {
        rad_re = (const float*)d_in[0];
        rad_im = (const float*)d_in[1];
        att_re = (const float*)d_in[2];
        att_im = (const float*)d_in[3];
        mode = OUT_INTERLEAVED;
    }
    f_re = (const float*)d_in[4];
    f_im = (const float*)d_in[5];

    float* out = (float*)d_out;

    accum_kernel<<<GRID_A, 256>>>(att_re, att_im, rad_re, rad_im);
    reduce1_kernel<<<dim3(34, RED_CHUNKS), 256>>>();
    reduce2_kernel<<<34, 256>>>();
    csi_kernel<<<F_SUB, 256>>>(f_re, f_im, out, mode);
}

// round 10
// speedup vs baseline: 1.2644x; 1.2644x over previous
#include <cuda_runtime.h>

// Problem constants
#define D_TOT   1296
#define K_PTS   64
#define R_RANK  16
#define F_SUB   408
#define DT      (200.0f / 64.0f)
#define D_PER_BLOCK 3
#define GRID_A  (D_TOT / D_PER_BLOCK)      // 432
#define OUT_SCALE (DT / (float)D_TOT)

#define OUT_INTERLEAVED 0
#define OUT_REAL_ONLY   1

// Per-block partials, fully overwritten every replay (no zeroing, no atomics).
// Layout per block: [tid*32 + 0..15] = T_re, [tid*32 + 16..31] = T_im,
//                   [8192 + tid] = M1_re, [8448 + tid] = M1_im.
#define PART_LEN 8704
#define RED_CHUNKS 12
#define RED_BPC (GRID_A / RED_CHUNKS)      // 36
__device__ __align__(16) float g_part[GRID_A][PART_LEN];
__device__ __align__(16) float g_part2[RED_CHUNKS][PART_LEN];
__device__ __align__(16) float g_acc[PART_LEN];

// ---- kernel A: accumulate T[i,j,l] and M1[i,j] over (d,k) ----
__global__ __launch_bounds__(256) void accum_kernel(
    const float* __restrict__ att_re, const float* __restrict__ att_im,
    const float* __restrict__ rad_re, const float* __restrict__ rad_im)
{
    __shared__ __align__(16) float2 s_a[K_PTS * R_RANK];   // att interleaved
    __shared__ __align__(16) float2 s_b[K_PTS * R_RANK];   // rad interleaved
    __shared__ __align__(16) float  s_cre[K_PTS * R_RANK];
    __shared__ __align__(16) float  s_cim[K_PTS * R_RANK];
    __shared__ float s_chunk[2][4][16];                    // scan partials

    const int tid = threadIdx.x;
    const int i = tid >> 4;
    const int j = tid & 15;

    float tre[16], tim[16];
#pragma unroll
    for (int l = 0; l < 16; ++l) { tre[l] = 0.0f; tim[l] = 0.0f; }
    float m1r = 0.0f, m1i = 0.0f;

    for (int dd = 0; dd < D_PER_BLOCK; ++dd) {
        const int d = blockIdx.x * D_PER_BLOCK + dd;
        const long base4 = (long)d * (K_PTS * R_RANK / 4);
        {
            float4 ar4 = reinterpret_cast<const float4*>(att_re)[base4 + tid];
            float4 ai4 = reinterpret_cast<const float4*>(att_im)[base4 + tid];
            float4 br4 = reinterpret_cast<const float4*>(rad_re)[base4 + tid];
            float4 bi4 = reinterpret_cast<const float4*>(rad_im)[base4 + tid];
            const int o = tid * 4;
            s_a[o + 0] = make_float2(ar4.x, ai4.x);
            s_a[o + 1] = make_float2(ar4.y, ai4.y);
            s_a[o + 2] = make_float2(ar4.z, ai4.z);
            s_a[o + 3] = make_float2(ar4.w, ai4.w);
            s_b[o + 0] = make_float2(br4.x, bi4.x);
            s_b[o + 1] = make_float2(br4.y, bi4.y);
            s_b[o + 2] = make_float2(br4.z, bi4.z);
            s_b[o + 3] = make_float2(br4.w, bi4.w);
        }
        __syncthreads();

        // Two-phase parallel cumsum: c[k][l] = DT * cumsum_k(att[k][l]).
        const int l_s = tid & 15;
        const int plane = (tid >> 4) & 1;
        const int q = tid >> 5;
        if (tid < 128) {
            float sum = 0.0f;
#pragma unroll
            for (int kk = 0; kk < 16; ++kk) {
                float2 v = s_a[(q * 16 + kk) * 16 + l_s];
                sum += plane ? v.y : v.x;
            }
            s_chunk[plane][q][l_s] = sum;
        }
        __syncthreads();
        if (tid < 128) {
            float run = 0.0f;
#pragma unroll
            for (int qq = 0; qq < 3; ++qq)
                if (qq < q) run += s_chunk[plane][qq][l_s];
            float* dst = plane ? s_cim : s_cre;
#pragma unroll
            for (int kk = 0; kk < 16; ++kk) {
                float2 v = s_a[(q * 16 + kk) * 16 + l_s];
                run += plane ? v.y : v.x;
                dst[(q * 16 + kk) * 16 + l_s] = DT * run;
            }
        }
        __syncthreads();

        // k = 0 peel: first order (M1) only
        {
            float2 a = s_a[j];
            float2 b = s_b[i];
            m1r += b.x * a.x - b.y * a.y;
            m1i -= b.x * a.y + b.y * a.x;
        }

#pragma unroll 2
        for (int k = 1; k < K_PTS; ++k) {
            float2 a = s_a[k * 16 + j];
            float2 b = s_b[k * 16 + i];
            // w = conj(rad_i) * conj(att_j)
            float wr = fmaf(b.x, a.x, -b.y * a.y);
            float wi = -fmaf(b.x, a.y, b.y * a.x);
            m1r += wr;
            m1i += wi;

            const float4* cr4 = reinterpret_cast<const float4*>(s_cre + k * 16);
            const float4* ci4 = reinterpret_cast<const float4*>(s_cim + k * 16);
#pragma unroll
            for (int p = 0; p < 4; ++p) {
                float4 cr = cr4[p];
                float4 ci = ci4[p];
                tre[4*p+0] = fmaf(wr, cr.x, fmaf(-wi, ci.x, tre[4*p+0]));
                tim[4*p+0] = fmaf(wr, ci.x, fmaf( wi, cr.x, tim[4*p+0]));
                tre[4*p+1] = fmaf(wr, cr.y, fmaf(-wi, ci.y, tre[4*p+1]));
                tim[4*p+1] = fmaf(wr, ci.y, fmaf( wi, cr.y, tim[4*p+1]));
                tre[4*p+2] = fmaf(wr, cr.z, fmaf(-wi, ci.z, tre[4*p+2]));
                tim[4*p+2] = fmaf(wr, ci.z, fmaf( wi, cr.z, tim[4*p+2]));
                tre[4*p+3] = fmaf(wr, cr.w, fmaf(-wi, ci.w, tre[4*p+3]));
                tim[4*p+3] = fmaf(wr, ci.w, fmaf( wi, cr.w, tim[4*p+3]));
            }
        }
        __syncthreads();   // before next dd overwrites shared
    }

    // Write per-block partials (coalesced float4 stores)
    float* pT = g_part[blockIdx.x] + tid * 32;
#pragma unroll
    for (int p = 0; p < 4; ++p)
        reinterpret_cast<float4*>(pT)[p] =
            make_float4(tre[4*p], tre[4*p+1], tre[4*p+2], tre[4*p+3]);
#pragma unroll
    for (int p = 0; p < 4; ++p)
        reinterpret_cast<float4*>(pT + 16)[p] =
            make_float4(tim[4*p], tim[4*p+1], tim[4*p+2], tim[4*p+3]);
    g_part[blockIdx.x][8192 + tid] = m1r;
    g_part[blockIdx.x][8448 + tid] = m1i;
}

// ---- reduce stage 1: fold 36 partials per chunk (grid 34 x 12) ----
__global__ __launch_bounds__(256) void reduce1_kernel() {
    const int v = blockIdx.x * 256 + threadIdx.x;   // 34*256 = 8704
    const int c = blockIdx.y;
    const int b0 = c * RED_BPC;
    float s0 = 0.f, s1 = 0.f, s2 = 0.f, s3 = 0.f, s4 = 0.f, s5 = 0.f;
#pragma unroll 1
    for (int n = 0; n < RED_BPC; n += 6) {          // 36 = 6*6
        s0 += g_part[b0 + n + 0][v];
        s1 += g_part[b0 + n + 1][v];
        s2 += g_part[b0 + n + 2][v];
        s3 += g_part[b0 + n + 3][v];
        s4 += g_part[b0 + n + 4][v];
        s5 += g_part[b0 + n + 5][v];
    }
    g_part2[c][v] = ((s0 + s1) + (s2 + s3)) + (s4 + s5);
}

// ---- reduce stage 2: fold 12 chunk sums (grid 34) ----
__global__ __launch_bounds__(256) void reduce2_kernel() {
    const int v = blockIdx.x * 256 + threadIdx.x;
    float s = 0.0f;
#pragma unroll
    for (int c = 0; c < RED_CHUNKS; ++c) s += g_part2[c][v];
    g_acc[v] = s;
}

// ---- kernel B: warp-per-f contraction, no block barriers ----
// grid 51 x 256 threads; warp w handles f = blockIdx.x*8 + w.
__global__ __launch_bounds__(256) void csi_kernel(
    const float* __restrict__ f_re, const float* __restrict__ f_im,
    float* __restrict__ out, int mode)
{
    const int lane = threadIdx.x & 31;
    const int f = blockIdx.x * 8 + (threadIdx.x >> 5);

    // lanes 0..15 hold f_re[l], lanes 16..31 hold f_im[l]
    float fv = (lane < 16) ? f_re[f * R_RANK + lane]
                           : f_im[f * R_RANK + (lane - 16)];

    // broadcast into per-lane register arrays (compile-time indexed)
    float fr[16], fi[16];
#pragma unroll
    for (int l = 0; l < 16; ++l) {
        fr[l] = __shfl_sync(0xFFFFFFFFu, fv, l);
        fi[l] = __shfl_sync(0xFFFFFFFFu, fv, 16 + l);
    }

    float accr = 0.0f, acci = 0.0f;
#pragma unroll
    for (int p = 0; p < 8; ++p) {
        const int ij = lane + 32 * p;
        const int i = ij >> 4;
        const int j = ij & 15;

        // inner = M1[ij] + sum_l f_l * T[ij][l]
        float sr = g_acc[8192 + ij];
        float si = g_acc[8448 + ij];
        const float4* tr4 = reinterpret_cast<const float4*>(g_acc + ij * 32);
        const float4* ti4 = reinterpret_cast<const float4*>(g_acc + ij * 32 + 16);
#pragma unroll
        for (int q = 0; q < 4; ++q) {
            float4 tr = tr4[q];
            float4 ti = ti4[q];
            sr = fmaf(tr.x, fr[4*q+0], fmaf(-ti.x, fi[4*q+0], sr));
            si = fmaf(tr.x, fi[4*q+0], fmaf( ti.x, fr[4*q+0], si));
            sr = fmaf(tr.y, fr[4*q+1], fmaf(-ti.y, fi[4*q+1], sr));
            si = fmaf(tr.y, fi[4*q+1], fmaf( ti.y, fr[4*q+1], si));
            sr = fmaf(tr.z, fr[4*q+2], fmaf(-ti.z, fi[4*q+2], sr));
            si = fmaf(tr.z, fi[4*q+2], fmaf( ti.z, fr[4*q+2], si));
            sr = fmaf(tr.w, fr[4*q+3], fmaf(-ti.w, fi[4*q+3], sr));
            si = fmaf(tr.w, fi[4*q+3], fmaf( ti.w, fr[4*q+3], si));
        }
        // val = (f_i * f_j) * inner
        float pr = fr[0], pi_;   // placeholders replaced below
        float fir = fr[0], fii = fi[0], fjr = fr[0], fji = fi[0];
        // i, j are lane-dependent but small; select from register arrays
        // via shfl on fv (variable-index shuffle).
        fir = __shfl_sync(0xFFFFFFFFu, fv, i);
        fii = __shfl_sync(0xFFFFFFFFu, fv, 16 + i);
        fjr = __shfl_sync(0xFFFFFFFFu, fv, j);
        fji = __shfl_sync(0xFFFFFFFFu, fv, 16 + j);
        pr  = fir * fjr - fii * fji;
        pi_ = fir * fji + fii * fjr;
        accr += pr * sr - pi_ * si;
        acci += pr * si + pi_ * sr;
    }

    // warp reduction
#pragma unroll
    for (int off = 16; off > 0; off >>= 1) {
        accr += __shfl_down_sync(0xFFFFFFFFu, accr, off);
        acci += __shfl_down_sync(0xFFFFFFFFu, acci, off);
    }
    if (lane == 0) {
        float re = accr * OUT_SCALE;
        float im = acci * OUT_SCALE;
        if (mode == OUT_REAL_ONLY) {
            out[f] = re;                       // float32(csi) == Re(csi)
        } else {
            out[2 * f]     = re;
            out[2 * f + 1] = im;
        }
    }
}

extern "C" void kernel_launch(void* const* d_in, const int* in_sizes, int n_in,
                              void* d_out, int out_size)
{
    // Established (round 6 PASS): out_size == 408 -> real-part-only output,
    // inputs in dict/signature order.
    const float *att_re, *att_im, *rad_re, *rad_im, *f_re, *f_im;
    int mode;

    if (out_size == F_SUB) {
        att_re = (const float*)d_in[0];
        att_im = (const float*)d_in[1];
        rad_re = (const float*)d_in[2];
        rad_im = (const float*)d_in[3];
        mode = OUT_REAL_ONLY;
    } else {
        rad_re = (const float*)d_in[0];
        rad_im = (const float*)d_in[1];
        att_re = (const float*)d_in[2];
        att_im = (const float*)d_in[3];
        mode = OUT_INTERLEAVED;
    }
    f_re = (const float*)d_in[4];
    f_im = (const float*)d_in[5];

    float* out = (float*)d_out;

    accum_kernel<<<GRID_A, 256>>>(att_re, att_im, rad_re, rad_im);
    reduce1_kernel<<<dim3(34, RED_CHUNKS), 256>>>();
    reduce2_kernel<<<34, 256>>>();
    csi_kernel<<<51, 256>>>(f_re, f_im, out, mode);
}